// round 14
// baseline (speedup 1.0000x reference)
#include <cuda_runtime.h>
#include <cuda_bf16.h>
#include <cstdint>

#define NM     512
#define BATCH  32
#define DIMK   64
#define BIGF   1e30f
#define SENTU  0x7fc00000u

// Packed D (pre-scaled by log2 e): g_Dq[b][W][u][k] as float2.
// W = warp row-group (rows 64W+2k, 64W+2k+1), u = local step, col j = u-2k.
#define UROWS 592
__device__ __align__(16) float g_Dq[(size_t)BATCH * 8 * UROWS * 64];

// Per-tile ready flags: g_flag[b*64 + W*8 + jt]. BSS zero; reset by consumer.
__device__ int g_flag[BATCH * 64];

// Boundary rings: producer (warp w) publishes v1(u-1) at slot u.
// value(col c) lives at slot c+63. Slots 0..575 written; rest preinit BIG.
#define RING 656

__device__ __forceinline__ float ex2f(float x) {
    float r; asm("ex2.approx.f32 %0, %1;" : "=f"(r) : "f"(x)); return r;
}
__device__ __forceinline__ float lg2f(float x) {
    float r; asm("lg2.approx.f32 %0, %1;" : "=f"(r) : "f"(x)); return r;
}
// smem spin (raw backward branch, no BSSY): wait until *p != sentinel.
__device__ __forceinline__ float spinv(const float* p) {
    unsigned a = (unsigned)__cvta_generic_to_shared(p);
    unsigned v;
    asm volatile(
        "{\n\t.reg .pred sp;\n"
        "SPINS%=:\n\t"
        "ld.volatile.shared.b32 %0, [%1];\n\t"
        "setp.eq.u32 sp, %0, 0x7fc00000;\n\t"
        "@sp bra SPINS%=;\n\t}"
        : "=r"(v) : "r"(a) : "memory");
    return __uint_as_float(v);
}
__device__ __forceinline__ void sts_vol(float* p, float v) {
    unsigned a = (unsigned)__cvta_generic_to_shared(p);
    asm volatile("st.volatile.shared.b32 [%0], %1;" :: "r"(a), "f"(v) : "memory");
}
__device__ __forceinline__ int ldacq(const int* p) {
    int v;
    asm volatile("ld.acquire.gpu.global.b32 %0, [%1];" : "=r"(v) : "l"(p) : "memory");
    return v;
}
__device__ __forceinline__ void spin_flag(const int* p) {
    int v;
    asm volatile(
        "{\n\t.reg .pred fp;\n"
        "FSPIN%=:\n\t"
        "ld.acquire.gpu.global.b32 %0, [%1];\n\t"
        "setp.eq.s32 fp, %0, 0;\n\t"
        "@fp bra FSPIN%=;\n\t}"
        : "=r"(v) : "l"(p) : "memory");
}

union SmemU {
    struct {
        float Xs[64 * 68];
        float Ys[64 * 68];
        float x2s[64];
        float y2s[64];
        float stage[64 * 66];
    } pd;
    float rings[9 * RING];
};

// ---------------------------------------------------------------------------
// Fused kernel. Blocks 0..31: persistent sdtw wavefront CTAs (one per batch).
// Blocks 32..2079: pairdist tiles, j-tile outermost so early columns land
// first. Producer->consumer handoff via acquire flags, polled 64 steps early.
// ---------------------------------------------------------------------------
__global__ void __launch_bounds__(256) fused_kernel(
    const float* __restrict__ X, const float* __restrict__ Y,
    float* __restrict__ out)
{
    __shared__ SmemU smem;
    const int bid = blockIdx.x;
    const int tid = threadIdx.x;

    if (bid >= 32) {
        // =================== pairdist tile ===================
        const int p  = bid - 32;
        const int jt = p >> 8;          // j-tile, outermost in schedule
        const int b  = (p >> 3) & 31;
        const int W  = p & 7;           // i-tile == warp row-group
        const int i0 = W * 64;
        const int j0 = jt * 64;

        float* Xs = smem.pd.Xs;
        float* Ys = smem.pd.Ys;
        float* x2s = smem.pd.x2s;
        float* y2s = smem.pd.y2s;
        float* stage = smem.pd.stage;

        const float* Xb = X + ((size_t)b * NM + i0) * DIMK;
        const float* Yb = Y + ((size_t)b * NM + j0) * DIMK;

        for (int t = tid; t < 64 * 64; t += 256) {
            int r = t >> 6, k = t & 63;
            Xs[k * 68 + r] = Xb[r * DIMK + k];
            Ys[k * 68 + r] = Yb[r * DIMK + k];
        }
        __syncthreads();

        if (tid < 128) {
            int r = tid & 63;
            const float* S = (tid < 64) ? Xs : Ys;
            float acc = 0.f;
            #pragma unroll 8
            for (int k = 0; k < 64; ++k) { float v = S[k * 68 + r]; acc += v * v; }
            if (tid < 64) x2s[r] = acc; else y2s[r] = acc;
        }
        __syncthreads();

        const int tx = tid & 15, ty = tid >> 4;
        float acc[4][4];
        #pragma unroll
        for (int a = 0; a < 4; ++a)
            #pragma unroll
            for (int c = 0; c < 4; ++c) acc[a][c] = 0.f;

        #pragma unroll 8
        for (int k = 0; k < 64; ++k) {
            float4 xv = *(const float4*)&Xs[k * 68 + 4 * tx];
            float4 yv = *(const float4*)&Ys[k * 68 + 4 * ty];
            float xr[4] = {xv.x, xv.y, xv.z, xv.w};
            float yr[4] = {yv.x, yv.y, yv.z, yv.w};
            #pragma unroll
            for (int jj = 0; jj < 4; ++jj)
                #pragma unroll
                for (int ii = 0; ii < 4; ++ii)
                    acc[jj][ii] += yr[jj] * xr[ii];
        }

        const float L2E = 1.4426950408889634f;
        float4 x2v = *(const float4*)&x2s[4 * tx];
        float xr2[4] = {x2v.x, x2v.y, x2v.z, x2v.w};
        #pragma unroll
        for (int jj = 0; jj < 4; ++jj) {
            float y2 = y2s[4 * ty + jj];
            #pragma unroll
            for (int ii = 0; ii < 4; ++ii)
                stage[(4 * ty + jj) * 66 + 4 * tx + ii] =
                    (xr2[ii] + y2 - 2.f * acc[jj][ii]) * L2E;
        }
        __syncthreads();

        // Packed writeout: local step row c = jl + 2k; lane = k.
        const int wk   = tid >> 5;
        const int lane = tid & 31;
        float2* gout = (float2*)g_Dq + ((size_t)(b * 8 + W) * UROWS + j0) * 32;
        for (int c = wk; c < 126; c += 8) {
            int jl = c - 2 * lane;
            if ((unsigned)jl < 64u) {
                float2 q = *(const float2*)&stage[jl * 66 + 2 * lane];
                gout[(size_t)c * 32 + lane] = q;
            }
        }

        __syncthreads();
        __threadfence();
        if (tid == 0)
            *(volatile int*)&g_flag[b * 64 + W * 8 + jt] = 1;
        return;
    }

    // =================== sdtw wavefront (R11 core) ===================
    float* rings = smem.rings;
    const int b    = bid;
    const int w    = tid >> 5;
    const int lane = tid & 31;
    const bool is0  = (lane == 0);
    const bool is31 = (lane == 31);

    for (int t = tid; t < 9 * RING; t += 256) {
        int r = t / RING, s = t % RING;
        bool sent = (r >= 1) && (s < 576);
        rings[t] = sent ? __uint_as_float(SENTU) : BIGF;
    }
    __syncthreads();

    const int* flagp = g_flag + b * 64 + w * 8;
    spin_flag(flagp + 0);                        // tile 0 covers rows 0..125

    // D prefetch ring (float2 per lane per step).
    const float2* dp0 = (const float2*)g_Dq + (size_t)(b * 8 + w) * UROWS * 32 + lane;
    float2 dring[8];
    #pragma unroll
    for (int p = 0; p < 8; ++p) dring[p] = dp0[p * 32];
    const float2* dp = dp0 + 8 * 32;

    const float* rring = rings + w * RING;        // consumer: value(col c) at slot c+63
    float*       wring = rings + (w + 1) * RING;  // producer: iter u writes slot u

    // Prefill: P(-1) at slot 62, P(0) at slot 63.
    float pm1 = spinv(rring + 62);
    float p0  = spinv(rring + 63);
    if (lane != 0) { pm1 = BIGF; p0 = BIGF; }
    if (w == 0 && lane == 0) pm1 = 0.0f;          // origin: R[-1][-1] = 0
    float lo0  = fminf(pm1, p0), hi0 = fmaxf(pm1, p0);
    float pNow = p0;

    // First chunk: slots 64..71 = P(1..8).
    float bnd[8];
    {
        (void)spinv(rring + 71);
        float4 c0 = *(const float4*)(rring + 64);
        float4 c1 = *(const float4*)(rring + 68);
        bnd[0]=c0.x; bnd[1]=c0.y; bnd[2]=c0.z; bnd[3]=c0.w;
        bnd[4]=c1.x; bnd[5]=c1.y; bnd[6]=c1.z; bnd[7]=c1.w;
    }

    float v0p  = BIGF;                 // v0(u-1)
    float d2yp = 0.f;                  // d(u-1).y
    float lo1p = BIGF, hi1p = BIGF;    // min/max(v0(u-2), v1(u-2))
    float res  = 0.f;
    int   fpre = 1;                    // early-loaded flag for next tile

    for (int B = 0; B < 576; B += 8) {
        // Gate D prefetch on tile flags, polled 64 steps early (off-chain).
        if ((B & 63) == 0 && B < 448) fpre = ldacq(flagp + (B >> 6) + 1);
        if ((B & 63) == 56 && B < 448) { if (fpre == 0) spin_flag(flagp + ((B + 8) >> 6)); }

        #pragma unroll
        for (int x = 0; x < 8; ++x) {
            float2 d2 = dring[x];
            dring[x] = dp[x * 32];                 // prefetch step u+8

            // cell0(u): softmin(P(j-1), P(j), v0(u-1))
            float m0 = fminf(lo0, v0p);
            float x0 = fmaxf(lo0, v0p);
            float v0 = (d2.x + m0) - lg2f(ex2f(m0 - x0) + ex2f(m0 - hi0) + 1.0f);

            // cell1(u-1): softmin(v0(u-2), v1(u-2), v0(u-1)) -- parallel chain
            float m1  = fminf(lo1p, v0p);
            float x1  = fmaxf(lo1p, v0p);
            float v1m = (d2yp + m1) - lg2f(ex2f(m1 - x1) + ex2f(m1 - hi1p) + 1.0f);

            if (x == 6) { if (B == 568) res = v1m; }   // iter 574 -> v1(573) = R[511][511]

            if (is31) sts_vol(wring + (B + x), v1m);   // publish slot u

            float sh = __shfl_up_sync(0xffffffffu, v1m, 1);
            float newv = is0 ? bnd[x] : sh;            // P(u+1)

            if (x == 7) {                              // next chunk: slots B+72..79
                (void)spinv(rring + B + 79);
                float4 c0 = *(const float4*)(rring + B + 72);
                float4 c1 = *(const float4*)(rring + B + 76);
                bnd[0]=c0.x; bnd[1]=c0.y; bnd[2]=c0.z; bnd[3]=c0.w;
                bnd[4]=c1.x; bnd[5]=c1.y; bnd[6]=c1.z; bnd[7]=c1.w;
            }

            // rolls (off the v0 chain)
            lo1p = fminf(v0p, v1m);
            hi1p = fmaxf(v0p, v1m);
            lo0  = fminf(pNow, newv);
            hi0  = fmaxf(pNow, newv);
            pNow = newv;
            v0p  = v0;
            d2yp = d2.y;
        }
        dp += 8 * 32;
    }

    if (tid == 255)
        out[b] = res * 0.69314718055994531f;           // log2 -> natural domain

    // Reset this batch's flags so graph replays start clean.
    __syncthreads();
    if (tid < 64) g_flag[b * 64 + tid] = 0;
}

extern "C" void kernel_launch(void* const* d_in, const int* in_sizes, int n_in,
                              void* d_out, int out_size)
{
    (void)in_sizes; (void)n_in; (void)out_size;
    const float* X = (const float*)d_in[0];
    const float* Y = (const float*)d_in[1];
    float* out = (float*)d_out;

    fused_kernel<<<32 + BATCH * 64, 256>>>(X, Y, out);
}